// round 16
// baseline (speedup 1.0000x reference)
#include <cuda_runtime.h>

// ---------------------------------------------------------------------------
// R16: R14/R15 base + two-phase activation (MUFU burst / FMA burst).
// Pipe model: per warp-step fma ~276 cyc, MUFU ~320 cyc (20 tanh.f16x2 @rt16)
// -> MUFU and fma are CO-BINDING (~74%/~67%), explaining the R9-R15 plateau.
// This round separates each layer's activations into: phase A = all 8 gate
// tanhs of BOTH element-pairs issued back-to-back (pure MUFU burst), phase B
// = both pairs' cell updates + tanh(c) + h' (fma burst), maximizing
// cross-pair overlap of the two pipes. Op counts unchanged.
// Datapath: NE=4 as two f16x2 element-pairs, HFMA2 MACs, f16x2 cell,
// h'=2h weight folding (R15), packed shfl, x/Wout one-iteration prefetch.
// ---------------------------------------------------------------------------

#define T_STEPS 50
typedef unsigned int u32;
typedef unsigned long long ull;

__device__ __forceinline__ float ex2f(float x) {
    float r; asm("ex2.approx.f32 %0, %1;" : "=f"(r) : "f"(x)); return r;
}
__device__ __forceinline__ float rcpf(float x) {
    float r; asm("rcp.approx.f32 %0, %1;" : "=f"(r) : "f"(x)); return r;
}
__device__ __forceinline__ ull pk2(float lo, float hi) {
    ull r; asm("mov.b64 %0, {%1, %2};" : "=l"(r) : "f"(lo), "f"(hi)); return r;
}
__device__ __forceinline__ void upk2(ull v, float& lo, float& hi) {
    asm("mov.b64 {%0, %1}, %2;" : "=f"(lo), "=f"(hi) : "l"(v));
}
__device__ __forceinline__ ull ffma2(ull a, ull b, ull c) {
    ull d; asm("fma.rn.f32x2 %0, %1, %2, %3;" : "=l"(d) : "l"(a), "l"(b), "l"(c));
    return d;
}

// ---- f16x2 helpers: lo half = even element, hi half = odd element ----------
__device__ __forceinline__ u32 h2pack(float lo, float hi) {
    u32 p; asm("cvt.rn.f16x2.f32 %0, %1, %2;" : "=r"(p) : "f"(hi), "f"(lo));
    return p;
}
__device__ __forceinline__ u32 h2dup(float w) {      // (w, w)
    u32 p; asm("cvt.rn.f16x2.f32 %0, %1, %1;" : "=r"(p) : "f"(w));
    return p;
}
__device__ __forceinline__ ull h2f32x2(u32 p) {      // f16x2 -> packed f32x2
    float lo, hi;
    asm("{\n\t.reg .b16 l, h;\n\tmov.b32 {l, h}, %2;\n\t"
        "cvt.f32.f16 %0, l;\n\tcvt.f32.f16 %1, h;\n\t}"
        : "=f"(lo), "=f"(hi) : "r"(p));
    return pk2(lo, hi);
}
__device__ __forceinline__ u32 hfma2(u32 a, u32 b, u32 c) {
    u32 d; asm("fma.rn.f16x2 %0, %1, %2, %3;" : "=r"(d) : "r"(a), "r"(b), "r"(c));
    return d;
}
__device__ __forceinline__ u32 hmul2(u32 a, u32 b) {
    u32 d; asm("mul.rn.f16x2 %0, %1, %2;" : "=r"(d) : "r"(a), "r"(b)); return d;
}
__device__ __forceinline__ u32 hadd2(u32 a, u32 b) {
    u32 d; asm("add.rn.f16x2 %0, %1, %2;" : "=r"(d) : "r"(a), "r"(b)); return d;
}
__device__ __forceinline__ u32 h2tanh(u32 p) {
    u32 r; asm("tanh.approx.f16x2 %0, %1;" : "=r"(r) : "r"(p)); return r;
}

#define NP 2            // element-pairs per thread
#define NE (2 * NP)     // elements per thread
#define HALF2 0x38003800u

__global__ __launch_bounds__(128, 4) void lstm_2ph(
    const float* __restrict__ x,     // [B, T, 2]
    const float* __restrict__ Wih0,  // [16, 2]
    const float* __restrict__ Whh0,  // [16, 4]
    const float* __restrict__ bih0,
    const float* __restrict__ bhh0,
    const float* __restrict__ Wih1,  // [16, 4]
    const float* __restrict__ Whh1,  // [16, 4]
    const float* __restrict__ bih1,
    const float* __restrict__ bhh1,
    const float* __restrict__ Wout,  // [1, 200], col = t*4 + u
    const float* __restrict__ bout,
    float* __restrict__ out,
    int B)
{
    int g = blockIdx.x * 128 + threadIdx.x;
    int q = g >> 2;            // quad owns elements NE*q .. NE*q+NE-1
    int u = g & 3;             // hidden unit owned by this lane
    int eA = NE * q;
    if (eA >= B) return;
    int base = (threadIdx.x & 31) & ~3;

    // Gate rows for unit u (PyTorch order): i=u, f=4+u, g=8+u, o=12+u.
    // Row scale: sigmoid gates (i,f,o) x0.5 (tanh half-arg); g-gate x1.
    // Column scale: h-consuming weights x0.5 more (h' = 2h convention).
    const int   row[4] = { u, 4 + u, 8 + u, 12 + u };
    const float scl[4] = { 0.5f, 0.5f, 1.0f, 0.5f };

    u32 wi0h[4][2], wh0h[4][4], bh0[4];
    u32 wi1h[4][4], wh1h[4][4], bh1[4];
#pragma unroll
    for (int G = 0; G < 4; G++) {
        int r = row[G];
        float s = scl[G];
        float sh = 0.5f * s;     // h'-column compensation
#pragma unroll
        for (int k = 0; k < 2; k++)
            wi0h[G][k] = h2dup(s * __ldg(&Wih0[r * 2 + k]));   // x columns: raw
#pragma unroll
        for (int k = 0; k < 4; k++) {
            wh0h[G][k] = h2dup(sh * __ldg(&Whh0[r * 4 + k]));  // h0' columns
            wi1h[G][k] = h2dup(sh * __ldg(&Wih1[r * 4 + k]));  // h0' columns
            wh1h[G][k] = h2dup(sh * __ldg(&Whh1[r * 4 + k]));  // h1' columns
        }
        bh0[G] = h2dup(s * (__ldg(&bih0[r]) + __ldg(&bhh0[r])));
        bh1[G] = h2dup(s * (__ldg(&bih1[r]) + __ldg(&bhh1[r])));
    }

    // State: f16x2 cell per pair per layer; f16x2 h' broadcasts; f32x2 readout.
    u32 c20[NP], c21[NP];
    u32 hb0[NP][4], hb1[NP][4];
    ull z2[NP];
#pragma unroll
    for (int P = 0; P < NP; P++) {
        c20[P] = c21[P] = 0u;
        z2[P] = 0ull;
#pragma unroll
        for (int k = 0; k < 4; k++) { hb0[P][k] = 0u; hb1[P][k] = 0u; }
    }

    const float4* xb = reinterpret_cast<const float4*>(x + (size_t)eA * (T_STEPS * 2));

    // Prime the prefetch pipeline (x for tt=0 and Wout for t=0,1).
    float4 va0 = __ldg(&xb[0]);
    float4 vb0 = __ldg(&xb[0 + (T_STEPS / 2)]);
    float4 va1 = __ldg(&xb[0 + 2 * (T_STEPS / 2)]);
    float4 vb1 = __ldg(&xb[0 + 3 * (T_STEPS / 2)]);
    float wo  = __ldg(&Wout[0 * 4 + u]);
    float wo2 = __ldg(&Wout[1 * 4 + u]);

#pragma unroll 1
    for (int tt = 0; tt < T_STEPS / 2; ++tt) {
        // Pack CURRENT iteration's x (loads issued one iteration ago).
        u32 xp[NP][2][2];
        xp[0][0][0] = h2pack(va0.x, vb0.x);
        xp[0][0][1] = h2pack(va0.y, vb0.y);
        xp[0][1][0] = h2pack(va0.z, vb0.z);
        xp[0][1][1] = h2pack(va0.w, vb0.w);
        xp[1][0][0] = h2pack(va1.x, vb1.x);
        xp[1][0][1] = h2pack(va1.y, vb1.y);
        xp[1][1][0] = h2pack(va1.z, vb1.z);
        xp[1][1][1] = h2pack(va1.w, vb1.w);
        float woA = wo, woB = wo2;

        // Prefetch NEXT iteration (clamped; values unused on last iteration).
        int tn = (tt + 1 < T_STEPS / 2) ? (tt + 1) : tt;
        va0 = __ldg(&xb[tn]);
        vb0 = __ldg(&xb[tn + (T_STEPS / 2)]);
        va1 = __ldg(&xb[tn + 2 * (T_STEPS / 2)]);
        vb1 = __ldg(&xb[tn + 3 * (T_STEPS / 2)]);
        wo  = __ldg(&Wout[(2 * tn) * 4 + u]);
        wo2 = __ldg(&Wout[(2 * tn + 1) * 4 + u]);

#pragma unroll
        for (int s = 0; s < 2; s++) {
            u32 h20[NP], h21[NP];

            // ================= layer 0 =================
            // MAC phase (both pairs): x-terms first, h-terms after.
            u32 y[NP][4];
#pragma unroll
            for (int P = 0; P < NP; P++) {
#pragma unroll
                for (int G = 0; G < 4; G++) {
                    u32 a = hfma2(wi0h[G][0], xp[P][s][0], bh0[G]);
                    a = hfma2(wi0h[G][1], xp[P][s][1], a);
#pragma unroll
                    for (int k = 0; k < 4; k++)
                        a = hfma2(wh0h[G][k], hb0[P][k], a);
                    y[P][G] = a;
                }
            }
            // Phase A: MUFU burst — all 8 gate tanhs of both pairs.
            u32 tg_[NP][4];
#pragma unroll
            for (int P = 0; P < NP; P++)
#pragma unroll
                for (int G = 0; G < 4; G++)
                    tg_[P][G] = h2tanh(y[P][G]);
            // Phase B: fma burst — cell updates + tanh(c) + h' for both pairs.
#pragma unroll
            for (int P = 0; P < NP; P++) {
                u32 uu = hfma2(tg_[P][0], tg_[P][2], tg_[P][2]);  // 2*si*tg
                u32 vv = hfma2(tg_[P][1], c20[P], c20[P]);        // 2*sf*c
                c20[P] = hmul2(hadd2(uu, vv), HALF2);
                u32 tc = h2tanh(c20[P]);
                h20[P] = hfma2(tg_[P][3], tc, tc);                // h' = 2h
            }
            // packed shfl broadcast of layer0 h'
#pragma unroll
            for (int P = 0; P < NP; P++) {
#pragma unroll
                for (int k = 0; k < 4; k++)
                    hb0[P][k] = __shfl_sync(0xFFFFFFFFu, h20[P], base + k);
            }

            // ================= layer 1 =================
            // MAC phase: recurrent (old hb1) first, fresh hb0 last.
#pragma unroll
            for (int P = 0; P < NP; P++) {
#pragma unroll
                for (int G = 0; G < 4; G++) {
                    u32 a = hfma2(wh1h[G][0], hb1[P][0], bh1[G]);
#pragma unroll
                    for (int k = 1; k < 4; k++)
                        a = hfma2(wh1h[G][k], hb1[P][k], a);
#pragma unroll
                    for (int k = 0; k < 4; k++)
                        a = hfma2(wi1h[G][k], hb0[P][k], a);
                    y[P][G] = a;
                }
            }
            // Phase A: MUFU burst.
#pragma unroll
            for (int P = 0; P < NP; P++)
#pragma unroll
                for (int G = 0; G < 4; G++)
                    tg_[P][G] = h2tanh(y[P][G]);
            // Phase B: fma burst.
#pragma unroll
            for (int P = 0; P < NP; P++) {
                u32 uu = hfma2(tg_[P][0], tg_[P][2], tg_[P][2]);
                u32 vv = hfma2(tg_[P][1], c21[P], c21[P]);
                c21[P] = hmul2(hadd2(uu, vv), HALF2);
                u32 tc = h2tanh(c21[P]);
                h21[P] = hfma2(tg_[P][3], tc, tc);
            }

            // readout accumulates h' * w = 2*h*w (halved once at the end)
            float wcur = s ? woB : woA;
            ull wde = pk2(wcur, wcur);
#pragma unroll
            for (int P = 0; P < NP; P++) {
                z2[P] = ffma2(h2f32x2(h21[P]), wde, z2[P]);
#pragma unroll
                for (int k = 0; k < 4; k++)
                    hb1[P][k] = __shfl_sync(0xFFFFFFFFu, h21[P], base + k);
            }
        }
    }

    // quad reduction of readouts (z' = 2z); lane u==0 stores a coalesced float4
    float z[NE];
#pragma unroll
    for (int P = 0; P < NP; P++) upk2(z2[P], z[2 * P], z[2 * P + 1]);
#pragma unroll
    for (int e = 0; e < NE; e++) {
        z[e] += __shfl_xor_sync(0xFFFFFFFFu, z[e], 1);
        z[e] += __shfl_xor_sync(0xFFFFFFFFu, z[e], 2);
    }
    if (u == 0) {
        float bo = __ldg(&bout[0]);
        float4 r;
        r.x = rcpf(1.0f + ex2f(-1.442695040888963f * fmaf(0.5f, z[0], bo)));
        r.y = rcpf(1.0f + ex2f(-1.442695040888963f * fmaf(0.5f, z[1], bo)));
        r.z = rcpf(1.0f + ex2f(-1.442695040888963f * fmaf(0.5f, z[2], bo)));
        r.w = rcpf(1.0f + ex2f(-1.442695040888963f * fmaf(0.5f, z[3], bo)));
        *reinterpret_cast<float4*>(out + eA) = r;
    }
}

// ---------------------------------------------------------------------------
extern "C" void kernel_launch(void* const* d_in, const int* in_sizes, int n_in,
                              void* d_out, int out_size)
{
    const float* x    = (const float*)d_in[0];
    const float* Wih0 = (const float*)d_in[1];
    const float* Whh0 = (const float*)d_in[2];
    const float* bih0 = (const float*)d_in[3];
    const float* bhh0 = (const float*)d_in[4];
    const float* Wih1 = (const float*)d_in[5];
    const float* Whh1 = (const float*)d_in[6];
    const float* bih1 = (const float*)d_in[7];
    const float* bhh1 = (const float*)d_in[8];
    const float* Wout = (const float*)d_in[9];
    const float* bout = (const float*)d_in[10];

    int B = in_sizes[0] / (T_STEPS * 2);
    int threads = B;                   // 4 lanes per 4 elements
    int grid = (threads + 127) / 128;

    lstm_2ph<<<grid, 128>>>(x, Wih0, Whh0, bih0, bhh0,
                            Wih1, Whh1, bih1, bhh1,
                            Wout, bout, (float*)d_out, B);
}

// round 17
// speedup vs baseline: 1.0130x; 1.0130x over previous
#include <cuda_runtime.h>

// ---------------------------------------------------------------------------
// R17: R14 (champion: 150.4us) + 3-shfl butterfly exchange.
// The quad h-broadcast drops from 4 shfl.idx to 3 independent shfl.xor
// (masks 1,2,3; own value needs no shfl) by letting each lane receive units
// in order [u, u^1, u^2, u^3] and pre-permuting its h-consuming weight
// columns (w[G][p] = W[r][u^p]) at the prologue. Exact permutation ->
// bitwise-identical results; 16 -> 12 shfls per warp-step.
// Datapath otherwise byte-identical R14: NE=4 as two f16x2 element-pairs,
// HFMA2 MACs, f16x2 sigmoid-affine activations + cell, f32x2 readout,
// one-iteration x prefetch, 4 blocks/SM.
// ---------------------------------------------------------------------------

#define T_STEPS 50
typedef unsigned int u32;
typedef unsigned long long ull;

__device__ __forceinline__ float ex2f(float x) {
    float r; asm("ex2.approx.f32 %0, %1;" : "=f"(r) : "f"(x)); return r;
}
__device__ __forceinline__ float rcpf(float x) {
    float r; asm("rcp.approx.f32 %0, %1;" : "=f"(r) : "f"(x)); return r;
}
__device__ __forceinline__ ull pk2(float lo, float hi) {
    ull r; asm("mov.b64 %0, {%1, %2};" : "=l"(r) : "f"(lo), "f"(hi)); return r;
}
__device__ __forceinline__ void upk2(ull v, float& lo, float& hi) {
    asm("mov.b64 {%0, %1}, %2;" : "=f"(lo), "=f"(hi) : "l"(v));
}
__device__ __forceinline__ ull ffma2(ull a, ull b, ull c) {
    ull d; asm("fma.rn.f32x2 %0, %1, %2, %3;" : "=l"(d) : "l"(a), "l"(b), "l"(c));
    return d;
}

// ---- f16x2 helpers: lo half = even element, hi half = odd element ----------
__device__ __forceinline__ u32 h2pack(float lo, float hi) {
    u32 p; asm("cvt.rn.f16x2.f32 %0, %1, %2;" : "=r"(p) : "f"(hi), "f"(lo));
    return p;
}
__device__ __forceinline__ u32 h2dup(float w) {      // (w, w)
    u32 p; asm("cvt.rn.f16x2.f32 %0, %1, %1;" : "=r"(p) : "f"(w));
    return p;
}
__device__ __forceinline__ ull h2f32x2(u32 p) {      // f16x2 -> packed f32x2
    float lo, hi;
    asm("{\n\t.reg .b16 l, h;\n\tmov.b32 {l, h}, %2;\n\t"
        "cvt.f32.f16 %0, l;\n\tcvt.f32.f16 %1, h;\n\t}"
        : "=f"(lo), "=f"(hi) : "r"(p));
    return pk2(lo, hi);
}
__device__ __forceinline__ u32 hfma2(u32 a, u32 b, u32 c) {
    u32 d; asm("fma.rn.f16x2 %0, %1, %2, %3;" : "=r"(d) : "r"(a), "r"(b), "r"(c));
    return d;
}
__device__ __forceinline__ u32 hmul2(u32 a, u32 b) {
    u32 d; asm("mul.rn.f16x2 %0, %1, %2;" : "=r"(d) : "r"(a), "r"(b)); return d;
}
__device__ __forceinline__ u32 h2tanh(u32 p) {
    u32 r; asm("tanh.approx.f16x2 %0, %1;" : "=r"(r) : "r"(p)); return r;
}
// sigmoid of prescaled pre-act (x0.5 folded into weights): 0.5*tanh(y)+0.5
__device__ __forceinline__ u32 h2sig(u32 p) {
    u32 r;
    asm("{\n\ttanh.approx.f16x2 %0, %1;\n\t"
        "fma.rn.f16x2 %0, %0, %2, %2;\n\t}"
        : "=r"(r) : "r"(p), "r"(0x38003800u));
    return r;
}

// Pointwise LSTM block for one element-pair, all f16x2. c2 is f16x2 cell.
__device__ __forceinline__ u32 act_pair(u32 yi, u32 yf, u32 yg, u32 yo, u32& c2)
{
    u32 si = h2sig(yi);
    u32 sf = h2sig(yf);
    u32 so = h2sig(yo);
    u32 tg = h2tanh(yg);
    c2 = hfma2(sf, c2, hmul2(si, tg));
    return hmul2(so, h2tanh(c2));
}

#define NP 2            // element-pairs per thread
#define NE (2 * NP)     // elements per thread

__global__ __launch_bounds__(128, 4) void lstm_bfly(
    const float* __restrict__ x,     // [B, T, 2]
    const float* __restrict__ Wih0,  // [16, 2]
    const float* __restrict__ Whh0,  // [16, 4]
    const float* __restrict__ bih0,
    const float* __restrict__ bhh0,
    const float* __restrict__ Wih1,  // [16, 4]
    const float* __restrict__ Whh1,  // [16, 4]
    const float* __restrict__ bih1,
    const float* __restrict__ bhh1,
    const float* __restrict__ Wout,  // [1, 200], col = t*4 + u
    const float* __restrict__ bout,
    float* __restrict__ out,
    int B)
{
    int g = blockIdx.x * 128 + threadIdx.x;
    int q = g >> 2;            // quad owns elements NE*q .. NE*q+NE-1
    int u = g & 3;             // hidden unit owned by this lane
    int eA = NE * q;
    if (eA >= B) return;

    // Gate rows for unit u (PyTorch order): i=u, f=4+u, g=8+u, o=12+u.
    const int   row[4] = { u, 4 + u, 8 + u, 12 + u };
    const float scl[4] = { 0.5f, 0.5f, 1.0f, 0.5f };

    // Duplicated f16x2 weights. H-consuming columns are stored PERMUTED:
    // position p holds the column for unit (u ^ p), matching the butterfly
    // arrival order [own, xor1, xor2, xor3].
    u32 wi0h[4][2], wh0h[4][4], bh0[4];
    u32 wi1h[4][4], wh1h[4][4], bh1[4];
#pragma unroll
    for (int G = 0; G < 4; G++) {
        int r = row[G];
        float s = scl[G];
#pragma unroll
        for (int k = 0; k < 2; k++)
            wi0h[G][k] = h2dup(s * __ldg(&Wih0[r * 2 + k]));   // x cols: canonical
#pragma unroll
        for (int p = 0; p < 4; p++) {
            int k = u ^ p;                                      // permuted column
            wh0h[G][p] = h2dup(s * __ldg(&Whh0[r * 4 + k]));
            wi1h[G][p] = h2dup(s * __ldg(&Wih1[r * 4 + k]));
            wh1h[G][p] = h2dup(s * __ldg(&Whh1[r * 4 + k]));
        }
        bh0[G] = h2dup(s * (__ldg(&bih0[r]) + __ldg(&bhh0[r])));
        bh1[G] = h2dup(s * (__ldg(&bih1[r]) + __ldg(&bhh1[r])));
    }

    // State: f16x2 cell per pair per layer; f16x2 h in butterfly order.
    u32 c20[NP], c21[NP];
    u32 hb0[NP][4], hb1[NP][4];
    ull z2[NP];
#pragma unroll
    for (int P = 0; P < NP; P++) {
        c20[P] = c21[P] = 0u;
        z2[P] = 0ull;
#pragma unroll
        for (int k = 0; k < 4; k++) { hb0[P][k] = 0u; hb1[P][k] = 0u; }
    }

    const float4* xb = reinterpret_cast<const float4*>(x + (size_t)eA * (T_STEPS * 2));

    // Prime the x prefetch pipeline (loads for tt=0).
    float4 va0 = __ldg(&xb[0]);
    float4 vb0 = __ldg(&xb[0 + (T_STEPS / 2)]);
    float4 va1 = __ldg(&xb[0 + 2 * (T_STEPS / 2)]);
    float4 vb1 = __ldg(&xb[0 + 3 * (T_STEPS / 2)]);

#pragma unroll 1
    for (int tt = 0; tt < T_STEPS / 2; ++tt) {
        // Pack CURRENT iteration's x (loads issued one iteration ago).
        u32 xp[NP][2][2];
        xp[0][0][0] = h2pack(va0.x, vb0.x);
        xp[0][0][1] = h2pack(va0.y, vb0.y);
        xp[0][1][0] = h2pack(va0.z, vb0.z);
        xp[0][1][1] = h2pack(va0.w, vb0.w);
        xp[1][0][0] = h2pack(va1.x, vb1.x);
        xp[1][0][1] = h2pack(va1.y, vb1.y);
        xp[1][1][0] = h2pack(va1.z, vb1.z);
        xp[1][1][1] = h2pack(va1.w, vb1.w);

        // Prefetch NEXT iteration's x (clamped; unused on last iteration).
        int tn = (tt + 1 < T_STEPS / 2) ? (tt + 1) : tt;
        va0 = __ldg(&xb[tn]);
        vb0 = __ldg(&xb[tn + (T_STEPS / 2)]);
        va1 = __ldg(&xb[tn + 2 * (T_STEPS / 2)]);
        vb1 = __ldg(&xb[tn + 3 * (T_STEPS / 2)]);

        float wo  = __ldg(&Wout[(2 * tt) * 4 + u]);
        float wo2 = __ldg(&Wout[(2 * tt + 1) * 4 + u]);

#pragma unroll
        for (int s = 0; s < 2; s++) {
            u32 h20[NP], h21[NP];

            // ---- layer 0: x-terms first (ready early), h-terms after ----
#pragma unroll
            for (int P = 0; P < NP; P++) {
                u32 yi = hfma2(wi0h[0][0], xp[P][s][0], bh0[0]);
                u32 yf = hfma2(wi0h[1][0], xp[P][s][0], bh0[1]);
                u32 yg = hfma2(wi0h[2][0], xp[P][s][0], bh0[2]);
                u32 yo = hfma2(wi0h[3][0], xp[P][s][0], bh0[3]);
                yi = hfma2(wi0h[0][1], xp[P][s][1], yi);
                yf = hfma2(wi0h[1][1], xp[P][s][1], yf);
                yg = hfma2(wi0h[2][1], xp[P][s][1], yg);
                yo = hfma2(wi0h[3][1], xp[P][s][1], yo);
#pragma unroll
                for (int k = 0; k < 4; k++) {
                    yi = hfma2(wh0h[0][k], hb0[P][k], yi);
                    yf = hfma2(wh0h[1][k], hb0[P][k], yf);
                    yg = hfma2(wh0h[2][k], hb0[P][k], yg);
                    yo = hfma2(wh0h[3][k], hb0[P][k], yo);
                }
                h20[P] = act_pair(yi, yf, yg, yo, c20[P]);
            }
            // butterfly broadcast of layer0 h: 3 independent shfl.xor
#pragma unroll
            for (int P = 0; P < NP; P++) {
                hb0[P][0] = h20[P];
                hb0[P][1] = __shfl_xor_sync(0xFFFFFFFFu, h20[P], 1);
                hb0[P][2] = __shfl_xor_sync(0xFFFFFFFFu, h20[P], 2);
                hb0[P][3] = __shfl_xor_sync(0xFFFFFFFFu, h20[P], 3);
            }

            // ---- layer 1: recurrent (old hb1) first, fresh hb0 last ----
#pragma unroll
            for (int P = 0; P < NP; P++) {
                u32 yi = hfma2(wh1h[0][0], hb1[P][0], bh1[0]);
                u32 yf = hfma2(wh1h[1][0], hb1[P][0], bh1[1]);
                u32 yg = hfma2(wh1h[2][0], hb1[P][0], bh1[2]);
                u32 yo = hfma2(wh1h[3][0], hb1[P][0], bh1[3]);
#pragma unroll
                for (int k = 1; k < 4; k++) {
                    yi = hfma2(wh1h[0][k], hb1[P][k], yi);
                    yf = hfma2(wh1h[1][k], hb1[P][k], yf);
                    yg = hfma2(wh1h[2][k], hb1[P][k], yg);
                    yo = hfma2(wh1h[3][k], hb1[P][k], yo);
                }
#pragma unroll
                for (int k = 0; k < 4; k++) {
                    yi = hfma2(wi1h[0][k], hb0[P][k], yi);
                    yf = hfma2(wi1h[1][k], hb0[P][k], yf);
                    yg = hfma2(wi1h[2][k], hb0[P][k], yg);
                    yo = hfma2(wi1h[3][k], hb0[P][k], yo);
                }
                h21[P] = act_pair(yi, yf, yg, yo, c21[P]);
            }

            // readout (f32x2) + butterfly broadcast of layer1 h
            float wcur = s ? wo2 : wo;
            ull wde = pk2(wcur, wcur);
#pragma unroll
            for (int P = 0; P < NP; P++) {
                z2[P] = ffma2(h2f32x2(h21[P]), wde, z2[P]);
                hb1[P][0] = h21[P];
                hb1[P][1] = __shfl_xor_sync(0xFFFFFFFFu, h21[P], 1);
                hb1[P][2] = __shfl_xor_sync(0xFFFFFFFFu, h21[P], 2);
                hb1[P][3] = __shfl_xor_sync(0xFFFFFFFFu, h21[P], 3);
            }
        }
    }

    // quad reduction of readouts; lane u==0 stores a coalesced float4
    float z[NE];
#pragma unroll
    for (int P = 0; P < NP; P++) upk2(z2[P], z[2 * P], z[2 * P + 1]);
#pragma unroll
    for (int e = 0; e < NE; e++) {
        z[e] += __shfl_xor_sync(0xFFFFFFFFu, z[e], 1);
        z[e] += __shfl_xor_sync(0xFFFFFFFFu, z[e], 2);
    }
    if (u == 0) {
        float bo = __ldg(&bout[0]);
        float4 r;
        r.x = rcpf(1.0f + ex2f(-1.442695040888963f * (z[0] + bo)));
        r.y = rcpf(1.0f + ex2f(-1.442695040888963f * (z[1] + bo)));
        r.z = rcpf(1.0f + ex2f(-1.442695040888963f * (z[2] + bo)));
        r.w = rcpf(1.0f + ex2f(-1.442695040888963f * (z[3] + bo)));
        *reinterpret_cast<float4*>(out + eA) = r;
    }
}

// ---------------------------------------------------------------------------
extern "C" void kernel_launch(void* const* d_in, const int* in_sizes, int n_in,
                              void* d_out, int out_size)
{
    const float* x    = (const float*)d_in[0];
    const float* Wih0 = (const float*)d_in[1];
    const float* Whh0 = (const float*)d_in[2];
    const float* bih0 = (const float*)d_in[3];
    const float* bhh0 = (const float*)d_in[4];
    const float* Wih1 = (const float*)d_in[5];
    const float* Whh1 = (const float*)d_in[6];
    const float* bih1 = (const float*)d_in[7];
    const float* bhh1 = (const float*)d_in[8];
    const float* Wout = (const float*)d_in[9];
    const float* bout = (const float*)d_in[10];

    int B = in_sizes[0] / (T_STEPS * 2);
    int threads = B;                   // 4 lanes per 4 elements
    int grid = (threads + 127) / 128;

    lstm_bfly<<<grid, 128>>>(x, Wih0, Whh0, bih0, bhh0,
                             Wih1, Whh1, bih1, bhh1,
                             Wout, bout, (float*)d_out, B);
}